// round 15
// baseline (speedup 1.0000x reference)
#include <cuda_runtime.h>
#include <cuda_fp16.h>
#include <cuda_bf16.h>

// ---------------- problem constants ----------------
constexpr int NB     = 64;     // batches
constexpr int NODES_ = 116;    // nodes per batch
constexpr int Nn     = NB * NODES_;   // 7424
constexpr int Tt     = 256;
constexpr int Hh     = 32;
constexpr int Ee     = Nn * 128;      // 950272
constexpr int HID    = 64;
constexpr int BPB2   = NODES_ / 4;    // GRU blocks per batch = 29 (4 nodes/block)
constexpr int NGRUB  = NB * BPB2;     // 1856 GRU blocks
constexpr int NEDB   = Ee / 256;      // 3712 edge_deg blocks
constexpr int NCSRB  = Ee / 64;       // 14848 csr blocks (64 thr each)
constexpr int NPREB  = NEDB + 1;      // fused_pre grid (edge_deg | sort)

typedef unsigned long long ull;

// ---------------- device scratch (no cudaMalloc allowed) ----------------
__device__ __align__(16) float d_xwA[Nn * HID];   // layer input fp32 (ping)
__device__ __align__(16) __half d_xwhA[Nn * HID]; // layer input fp16 (ping)
__device__ __align__(16) float d_xwB[Nn * HID];   // layer input fp32 (pong)
__device__ __align__(16) __half d_xwhB[Nn * HID]; // layer input fp16 (pong)
__device__ float d_deg[Nn];
__device__ float d_dis[Nn];
__device__ float d_dis2[Nn];
__device__ __align__(16) int d_cnt[8192];         // padded for int4 scan loads
__device__ int   d_rowptr[Nn + 1];
__device__ int   d_cursor[Nn];
__device__ int   d_order[NB];                     // batches sorted by length desc
__device__ unsigned d_done;                       // fused_pre completion counter
__device__ __align__(16) ull d_edge[Ee];          // packed (src:int lo32, coef:f32 hi32)

// ---------------- helpers ----------------
__device__ __forceinline__ float sigm_(float a) {
    return __fdividef(1.0f, 1.0f + __expf(-a));
}
__device__ __forceinline__ float tanh_(float a) {
    return fmaf(-2.0f, __fdividef(1.0f, 1.0f + __expf(2.0f * a)), 1.0f);
}
__device__ __forceinline__ ull fma2_(ull a, ull b, ull c) {
    ull d;
    asm("fma.rn.f32x2 %0, %1, %2, %3;" : "=l"(d) : "l"(a), "l"(b), "l"(c));
    return d;
}
__device__ __forceinline__ ull pack2_(float lo, float hi) {
    ull d;
    asm("mov.b64 %0, {%1, %2};" : "=l"(d) : "f"(lo), "f"(hi));
    return d;
}
__device__ __forceinline__ float hsum2_(ull v) {
    float lo, hi;
    asm("mov.b64 {%0, %1}, %2;" : "=f"(lo), "=f"(hi) : "l"(v));
    return lo + hi;
}

// ---------------- 1) init deg/cnt/done ----------------
__global__ void init_kernel(float* __restrict__ deg, int* __restrict__ cnt) {
    int i = blockIdx.x * 256 + threadIdx.x;
    if (i == 0) d_done = 0;
    if (i < Nn) deg[i] = 1.0f;
    if (i < 8192) cnt[i] = 0;
}

// ---------------- 2) fused: edge_deg | sort, + last-block scan ----------------
__global__ void __launch_bounds__(256) fused_pre_kernel(
    const int* __restrict__ ei, const float* __restrict__ ea,
    float* __restrict__ deg, int* __restrict__ cnt,
    const int* __restrict__ lengths, int* __restrict__ order,
    int* __restrict__ rowptr, int* __restrict__ cursor,
    float* __restrict__ dis, float* __restrict__ dis2) {
    int bid = blockIdx.x;
    int tid = threadIdx.x;
    if (bid < NEDB) {
        // degree + in-count histogram
        int e = bid * 256 + tid;
        int dst = ei[Ee + e];
        atomicAdd(&deg[dst], ea[e]);
        atomicAdd(&cnt[dst], 1);
    } else {
        // rank-sort batches by length (descending)
        __shared__ int sl[NB];
        if (tid < NB) sl[tid] = lengths[tid];
        __syncthreads();
        if (tid < NB) {
            int v = sl[tid];
            int r = 0;
            #pragma unroll
            for (int m = 0; m < NB; m++) {
                int vm = sl[m];
                r += (vm > v) || (vm == v && m < tid);
            }
            order[r] = tid;
        }
    }

    // ---- last-block scan: rowptr/cursor + dis/dis2 ----
    __threadfence();
    __syncthreads();
    __shared__ unsigned rank_s;
    if (tid == 0) rank_s = atomicAdd(&d_done, 1u);
    __syncthreads();
    if (rank_s != NPREB - 1) return;
    __threadfence();    // acquire: all other blocks' writes now visible

    __shared__ int swarp[8];
    int wid = tid >> 5, lane = tid & 31;
    const int4* c4 = (const int4*)cnt;
    int pref[32];
    int s = 0;
    #pragma unroll
    for (int q = 0; q < 8; q++) {
        int4 v = c4[tid * 8 + q];
        pref[4 * q]     = s; s += v.x;
        pref[4 * q + 1] = s; s += v.y;
        pref[4 * q + 2] = s; s += v.z;
        pref[4 * q + 3] = s; s += v.w;
    }
    int sc = s;
    #pragma unroll
    for (int off = 1; off < 32; off <<= 1) {
        int n = __shfl_up_sync(0xffffffffu, sc, off);
        if (lane >= off) sc += n;
    }
    if (lane == 31) swarp[wid] = sc;
    __syncthreads();
    if (tid == 0) {
        int r = 0;
        #pragma unroll
        for (int w = 0; w < 8; w++) { r += swarp[w]; swarp[w] = r; }
    }
    __syncthreads();
    int base = (wid > 0 ? swarp[wid - 1] : 0) + (sc - s);  // exclusive prefix
    int idx0 = tid * 32;
    #pragma unroll
    for (int j = 0; j < 32; j++) {
        int idx = idx0 + j;
        if (idx < Nn) {
            int v = base + pref[j];
            rowptr[idx] = v;
            cursor[idx] = v;
        }
    }
    if (tid == 255) rowptr[Nn] = swarp[7];
    for (int i = tid; i < Nn; i += 256) {
        float dg = deg[i];
        float di = rsqrtf(dg);
        dis[i]  = di;
        dis2[i] = di * di;
    }
}

// ---------------- 3) merged: GRU+gemm0 (bids 0..NGRUB-1) | CSR fill (rest) ----------------
// GRU: 2 nodes per warp, register-resident packed weights (verified round-11 core).
// x read DIRECTLY from [N][T] layout: warp-uniform broadcast loads, one L1 line
// per 32 steps per node -> transpose eliminated.
// Epilogue: block computes xw0 = h @ W0^T for its own 4 nodes (no grid dep).
__global__ void __launch_bounds__(64) gru_csr_kernel(
    const float* __restrict__ x, const int* __restrict__ lengths,
    const int* __restrict__ order,
    const float* __restrict__ W_hh, const float* __restrict__ W_ih,
    const float* __restrict__ b_ih, const float* __restrict__ b_hh,
    const float* __restrict__ W0,
    float* __restrict__ xw_out, __half* __restrict__ xwh_out,
    const int* __restrict__ ei, const float* __restrict__ ea,
    const float* __restrict__ dis, int* __restrict__ cursor,
    ull* __restrict__ edge) {
    int bid = blockIdx.x;
    int tid = threadIdx.x;
    if (bid >= NGRUB) {
        // ---- CSR fill: one edge per thread ----
        int e = (bid - NGRUB) * 64 + tid;
        int src = ei[e];
        int dst = ei[Ee + e];
        float c = dis[src] * ea[e] * dis[dst];
        int pos = atomicAdd(&cursor[dst], 1);
        edge[pos] = ((ull)__float_as_uint(c) << 32) | (unsigned)src;
        return;
    }
    // ---- GRU ----
    __shared__ __align__(16) float sh_h[2][4][32];   // [buf][node-in-block][channel]
    int wid = tid >> 5;          // warp id (2 warps/block)
    int j   = tid & 31;          // hidden channel
    int batch = order[bid / BPB2];
    int nbase = batch * NODES_ + (bid % BPB2) * 4;
    int n0 = nbase + wid * 2;    // nodes n0, n0+1
    int len = lengths[batch];    // uniform across warp

    ull wR[16], wZ[16], wN[16];
    #pragma unroll
    for (int p = 0; p < 16; p++) {
        wR[p] = *(const ull*)&W_hh[(j     ) * 32 + 2 * p];
        wZ[p] = *(const ull*)&W_hh[(32 + j) * 32 + 2 * p];
        wN[p] = *(const ull*)&W_hh[(64 + j) * 32 + 2 * p];
    }
    float wiR = W_ih[j], wiZ = W_ih[32 + j], wiN = W_ih[64 + j];
    float bR  = b_ih[j]      + b_hh[j];
    float bZ  = b_ih[32 + j] + b_hh[32 + j];
    float bNx = b_ih[64 + j];
    float bNh = b_hh[64 + j];

    int ra = wid * 2, rb = wid * 2 + 1;
    float h0 = 0.0f, h1 = 0.0f;
    sh_h[0][ra][j] = 0.0f;
    sh_h[0][rb][j] = 0.0f;
    __syncwarp();

    const longlong2* hrdA = (const longlong2*)sh_h[0][ra];
    const longlong2* hrdB = (const longlong2*)sh_h[0][rb];
    float* hwrA = sh_h[1][ra];
    float* hwrB = sh_h[1][rb];

    const float* xpA = x + n0 * Tt;          // broadcast (uniform) row pointers
    const float* xpB = x + (n0 + 1) * Tt;
    float xn0 = __ldg(&xpA[0]);
    float xn1 = __ldg(&xpB[0]);
    for (int t = 0; t < len; t++) {
        float xt0 = xn0, xt1 = xn1;
        int tn = min(t + 1, Tt - 1);
        xn0 = __ldg(&xpA[tn]);               // L1-resident sequential prefetch
        xn1 = __ldg(&xpB[tn]);

        ull aR0 = pack2_(fmaf(xt0, wiR, bR), 0.0f);
        ull aZ0 = pack2_(fmaf(xt0, wiZ, bZ), 0.0f);
        ull aN0 = pack2_(bNh, 0.0f);
        ull aR1 = pack2_(fmaf(xt1, wiR, bR), 0.0f);
        ull aZ1 = pack2_(fmaf(xt1, wiZ, bZ), 0.0f);
        ull aN1 = pack2_(bNh, 0.0f);
        #pragma unroll
        for (int p = 0; p < 8; p++) {
            longlong2 ha = hrdA[p];          // broadcast LDS.128: 4 h of node 0
            longlong2 hb = hrdB[p];          // broadcast LDS.128: 4 h of node 1
            ull a0 = (ull)ha.x, a1 = (ull)ha.y;
            ull b0 = (ull)hb.x, b1 = (ull)hb.y;
            aR0 = fma2_(a0, wR[2 * p], aR0);
            aR1 = fma2_(b0, wR[2 * p], aR1);
            aZ0 = fma2_(a0, wZ[2 * p], aZ0);
            aZ1 = fma2_(b0, wZ[2 * p], aZ1);
            aN0 = fma2_(a0, wN[2 * p], aN0);
            aN1 = fma2_(b0, wN[2 * p], aN1);
            aR0 = fma2_(a1, wR[2 * p + 1], aR0);
            aR1 = fma2_(b1, wR[2 * p + 1], aR1);
            aZ0 = fma2_(a1, wZ[2 * p + 1], aZ0);
            aZ1 = fma2_(b1, wZ[2 * p + 1], aZ1);
            aN0 = fma2_(a1, wN[2 * p + 1], aN0);
            aN1 = fma2_(b1, wN[2 * p + 1], aN1);
        }
        float r0 = sigm_(hsum2_(aR0));
        float r1 = sigm_(hsum2_(aR1));
        float z0 = sigm_(hsum2_(aZ0));
        float z1 = sigm_(hsum2_(aZ1));
        float nn0 = tanh_(fmaf(xt0, wiN, bNx) + r0 * hsum2_(aN0));
        float nn1 = tanh_(fmaf(xt1, wiN, bNx) + r1 * hsum2_(aN1));
        h0 = fmaf(z0, h0 - nn0, nn0);        // (1-z)*nn + z*h
        h1 = fmaf(z1, h1 - nn1, nn1);
        hwrA[j] = h0;
        hwrB[j] = h1;
        __syncwarp();
        float* tA = (float*)hrdA; hrdA = (const longlong2*)hwrA; hwrA = tA;
        float* tB = (float*)hrdB; hrdB = (const longlong2*)hwrB; hwrB = tB;
    }

    // ---- gemm0 epilogue: xw[n][o] = sum_k h[n][k] * W0[o][k], 4 own nodes ----
    sh_h[0][ra][j] = h0;
    sh_h[0][rb][j] = h1;
    __syncthreads();
    int o = tid;                 // 0..63 output channel
    float4 w[8];
    #pragma unroll
    for (int q = 0; q < 8; q++)
        w[q] = ((const float4*)W0)[o * 8 + q];
    #pragma unroll
    for (int k = 0; k < 4; k++) {
        const float4* hv = (const float4*)sh_h[0][k];
        float acc = 0.0f;
        #pragma unroll
        for (int q = 0; q < 8; q++) {
            float4 hh = hv[q];   // broadcast LDS.128
            acc = fmaf(w[q].x, hh.x, acc);
            acc = fmaf(w[q].y, hh.y, acc);
            acc = fmaf(w[q].z, hh.z, acc);
            acc = fmaf(w[q].w, hh.w, acc);
        }
        int n = nbase + k;
        xw_out[n * 64 + o]  = acc;
        xwh_out[n * 64 + o] = __float2half(acc);
    }
}

// ---------------- 4-7) aggregation (+ fused next-layer gemm) ----------------
// 32 lanes per node: the two 16-lane half-warps split the edge list (even/odd
// 8-chunks) and combine via shfl_xor(16). 4 nodes/block -> 1856 blocks (2x
// parallelism vs 8 nodes/block). fp16 gathers, fp32 accumulation.
__global__ void __launch_bounds__(128) agg_kernel(
    const float* __restrict__ xw, const __half* __restrict__ xwh,
    const float* __restrict__ dis2,
    const int* __restrict__ rowptr, const ull* __restrict__ edge,
    const float* __restrict__ bias,
    const float* __restrict__ prelu_a, int layer,
    const float* __restrict__ Wnext,
    float* __restrict__ xw_out, __half* __restrict__ xwh_out,
    float* __restrict__ final_out) {
    __shared__ __align__(16) float sh_res[4][64];
    int tid = threadIdx.x;           // 128 -> 4 nodes/block, 32 lanes/node
    int w = tid >> 5;                // node slot in block
    int lane = tid & 31;
    int l = lane & 15;               // fp16x4 column (16 x 8B = 128B row)
    int g = lane >> 4;               // edge-list half (0 or 1)
    int n = blockIdx.x * 4 + w;

    const float4* __restrict__ xw4 = (const float4*)xw;
    const uint2* __restrict__ xh = (const uint2*)xwh;   // 4 halves per element
    float4 acc = {0.f, 0.f, 0.f, 0.f};
    if (g == 0) {                    // self term on half 0 only
        acc = xw4[n * 16 + l];
        float d2 = dis2[n];
        acc.x *= d2; acc.y *= d2; acc.z *= d2; acc.w *= d2;
    }

    int e0 = rowptr[n], e1 = rowptr[n + 1];
    for (int e = e0 + g * 8; e < e1; e += 16) {
        int cnt = e1 - e; if (cnt > 8) cnt = 8;
        #pragma unroll
        for (int m = 0; m < 8; m++) {
            if (m < cnt) {
                ull rm = __ldg(&edge[e + m]);     // uniform across 16 lanes
                int   sm = (int)(unsigned)rm;
                float cm = __uint_as_float((unsigned)(rm >> 32));
                uint2 hv = xh[sm * 16 + l];
                float2 f0 = __half22float2(*(__half2*)&hv.x);
                float2 f1 = __half22float2(*(__half2*)&hv.y);
                acc.x = fmaf(cm, f0.x, acc.x); acc.y = fmaf(cm, f0.y, acc.y);
                acc.z = fmaf(cm, f1.x, acc.z); acc.w = fmaf(cm, f1.y, acc.w);
            }
        }
    }
    // combine the two halves
    acc.x += __shfl_xor_sync(0xffffffffu, acc.x, 16);
    acc.y += __shfl_xor_sync(0xffffffffu, acc.y, 16);
    acc.z += __shfl_xor_sync(0xffffffffu, acc.z, 16);
    acc.w += __shfl_xor_sync(0xffffffffu, acc.w, 16);

    float4 b4 = ((const float4*)bias)[l];
    acc.x += b4.x; acc.y += b4.y; acc.z += b4.z; acc.w += b4.w;
    float a = prelu_a[layer];
    acc.x = (acc.x >= 0.f) ? acc.x : a * acc.x;
    acc.y = (acc.y >= 0.f) ? acc.y : a * acc.y;
    acc.z = (acc.z >= 0.f) ? acc.z : a * acc.z;
    acc.w = (acc.w >= 0.f) ? acc.w : a * acc.w;

    if (Wnext == nullptr) {          // final layer: write node embeddings
        if (g == 0) ((float4*)final_out)[n * 16 + l] = acc;
        return;
    }
    if (g == 0) ((float4*)sh_res[w])[l] = acc;
    __syncthreads();

    // ---- fused gemm: xw_{i+1}[n][o] = sum_k res[n][k] * Wnext[o][k], 4 own nodes ----
    int o = tid & 63;
    int half = tid >> 6;             // 0 or 1
    int nbase = blockIdx.x * 4;
    #pragma unroll
    for (int k = 0; k < 2; k++) {
        int nl = half * 2 + k;
        const float4* hv = (const float4*)sh_res[nl];
        const float4* wr = (const float4*)Wnext + o * 16;
        float acc2 = 0.0f;
        #pragma unroll
        for (int q = 0; q < 16; q++) {
            float4 hh = hv[q];
            float4 ww = wr[q];
            acc2 = fmaf(ww.x, hh.x, acc2);
            acc2 = fmaf(ww.y, hh.y, acc2);
            acc2 = fmaf(ww.z, hh.z, acc2);
            acc2 = fmaf(ww.w, hh.w, acc2);
        }
        int n2 = nbase + nl;
        xw_out[n2 * 64 + o]  = acc2;
        xwh_out[n2 * 64 + o] = __float2half(acc2);
    }
}

// ---------------- 8) graph mean pooling ----------------
__global__ void graph_kernel(const float* __restrict__ node_emb, float* __restrict__ gout) {
    int b = blockIdx.x;   // 64
    int d = threadIdx.x;  // 64
    float s = 0.0f;
    #pragma unroll 8
    for (int i = 0; i < NODES_; i++)
        s += node_emb[(b * NODES_ + i) * 64 + d];
    gout[b * 64 + d] = s * (1.0f / (float)NODES_);
}

// ---------------- launch (8 kernels, single stream) ----------------
extern "C" void kernel_launch(void* const* d_in, const int* in_sizes, int n_in,
                              void* d_out, int out_size) {
    const float* x       = (const float*)d_in[0];
    const int*   ei      = (const int*)d_in[1];
    const float* ea      = (const float*)d_in[2];
    const int*   lengths = (const int*)d_in[3];
    // d_in[4] = batch (unused; batch[n] == n / NODES_)
    const float* W_ih    = (const float*)d_in[5];
    const float* W_hh    = (const float*)d_in[6];
    const float* b_ih    = (const float*)d_in[7];
    const float* b_hh    = (const float*)d_in[8];
    const float* g_w0    = (const float*)d_in[9];
    const float* g_b0    = (const float*)d_in[10];
    const float* g_ws    = (const float*)d_in[11];
    const float* g_bs    = (const float*)d_in[12];
    const float* prelu_a = (const float*)d_in[13];
    float* out = (float*)d_out;

    float *xwA, *xwB, *deg, *dis, *dis2;
    __half *xwhA, *xwhB;
    int *cnt, *rowptr, *cursor, *order;
    ull* edge;
    cudaGetSymbolAddress((void**)&xwA,    d_xwA);
    cudaGetSymbolAddress((void**)&xwhA,   d_xwhA);
    cudaGetSymbolAddress((void**)&xwB,    d_xwB);
    cudaGetSymbolAddress((void**)&xwhB,   d_xwhB);
    cudaGetSymbolAddress((void**)&deg,    d_deg);
    cudaGetSymbolAddress((void**)&dis,    d_dis);
    cudaGetSymbolAddress((void**)&dis2,   d_dis2);
    cudaGetSymbolAddress((void**)&cnt,    d_cnt);
    cudaGetSymbolAddress((void**)&rowptr, d_rowptr);
    cudaGetSymbolAddress((void**)&cursor, d_cursor);
    cudaGetSymbolAddress((void**)&order,  d_order);
    cudaGetSymbolAddress((void**)&edge,   d_edge);

    // 1: init deg/cnt/done
    init_kernel<<<8192 / 256, 256>>>(deg, cnt);
    // 2: fused edge_deg | sort  (+ last-block scan)
    fused_pre_kernel<<<NPREB, 256>>>(ei, ea, deg, cnt, lengths, order,
                                     rowptr, cursor, dis, dis2);
    // 3: merged GRU+gemm0 | CSR fill  (x read directly, no transpose)
    gru_csr_kernel<<<NGRUB + NCSRB, 64>>>(x, lengths, order, W_hh, W_ih, b_ih, b_hh,
                                          g_w0, xwA, xwhA, ei, ea, dis, cursor, edge);
    // 4-7: agg layers (each fuses the next layer's gemm); A/B ping-pong
    agg_kernel<<<Nn / 4, 128>>>(xwA, xwhA, dis2, rowptr, edge, g_b0, prelu_a, 0,
                                g_ws + 0 * 64 * 64, xwB, xwhB, nullptr);      // profiled
    agg_kernel<<<Nn / 4, 128>>>(xwB, xwhB, dis2, rowptr, edge, g_bs + 0 * 64, prelu_a, 1,
                                g_ws + 1 * 64 * 64, xwA, xwhA, nullptr);
    agg_kernel<<<Nn / 4, 128>>>(xwA, xwhA, dis2, rowptr, edge, g_bs + 1 * 64, prelu_a, 2,
                                g_ws + 2 * 64 * 64, xwB, xwhB, nullptr);
    agg_kernel<<<Nn / 4, 128>>>(xwB, xwhB, dis2, rowptr, edge, g_bs + 2 * 64, prelu_a, 3,
                                nullptr, nullptr, nullptr, out);
    // 8: graph embedding appended after node embeddings
    graph_kernel<<<NB, 64>>>(out, out + Nn * 64);
}

// round 16
// speedup vs baseline: 1.1293x; 1.1293x over previous
#include <cuda_runtime.h>
#include <cuda_fp16.h>
#include <cuda_bf16.h>

// ---------------- problem constants ----------------
constexpr int NB     = 64;     // batches
constexpr int NODES_ = 116;    // nodes per batch
constexpr int Nn     = NB * NODES_;   // 7424
constexpr int Tt     = 256;
constexpr int Hh     = 32;
constexpr int Ee     = Nn * 128;      // 950272
constexpr int HID    = 64;
constexpr int BPB2   = NODES_ / 4;    // GRU blocks per batch = 29 (4 nodes/block)
constexpr int NGRUB  = NB * BPB2;     // 1856 GRU blocks
constexpr int NEDB   = Ee / 256;      // 3712 edge_deg blocks
constexpr int NCSRB  = Ee / 64;       // 14848 csr blocks (64 thr each)
constexpr int NPREB  = NEDB + 1;      // fused_pre grid (edge_deg | sort)

typedef unsigned long long ull;

// ---------------- device scratch (no cudaMalloc allowed) ----------------
__device__ __align__(16) float d_xwA[Nn * HID];   // layer input fp32 (ping)
__device__ __align__(16) __half d_xwhA[Nn * HID]; // layer input fp16 (ping)
__device__ __align__(16) float d_xwB[Nn * HID];   // layer input fp32 (pong)
__device__ __align__(16) __half d_xwhB[Nn * HID]; // layer input fp16 (pong)
__device__ float d_deg[Nn];
__device__ float d_dis[Nn];
__device__ float d_dis2[Nn];
__device__ __align__(16) int d_cnt[8192];         // padded for int4 scan loads
__device__ int   d_rowptr[Nn + 1];
__device__ int   d_cursor[Nn];
__device__ int   d_order[NB];                     // batches sorted by length desc
__device__ unsigned d_done;                       // fused_pre completion counter
__device__ __align__(16) ull d_edge[Ee];          // packed (src:int lo32, coef:f32 hi32)

// ---------------- helpers ----------------
__device__ __forceinline__ float sigm_(float a) {
    return __fdividef(1.0f, 1.0f + __expf(-a));
}
__device__ __forceinline__ float tanh_(float a) {
    return fmaf(-2.0f, __fdividef(1.0f, 1.0f + __expf(2.0f * a)), 1.0f);
}
__device__ __forceinline__ ull fma2_(ull a, ull b, ull c) {
    ull d;
    asm("fma.rn.f32x2 %0, %1, %2, %3;" : "=l"(d) : "l"(a), "l"(b), "l"(c));
    return d;
}
__device__ __forceinline__ ull pack2_(float lo, float hi) {
    ull d;
    asm("mov.b64 %0, {%1, %2};" : "=l"(d) : "f"(lo), "f"(hi));
    return d;
}
__device__ __forceinline__ float hsum2_(ull v) {
    float lo, hi;
    asm("mov.b64 {%0, %1}, %2;" : "=f"(lo), "=f"(hi) : "l"(v));
    return lo + hi;
}

// ---------------- 1) init deg/cnt/done ----------------
__global__ void init_kernel(float* __restrict__ deg, int* __restrict__ cnt) {
    int i = blockIdx.x * 256 + threadIdx.x;
    if (i == 0) d_done = 0;
    if (i < Nn) deg[i] = 1.0f;
    if (i < 8192) cnt[i] = 0;
}

// ---------------- 2) fused: edge_deg | sort, + last-block scan ----------------
__global__ void __launch_bounds__(256) fused_pre_kernel(
    const int* __restrict__ ei, const float* __restrict__ ea,
    float* __restrict__ deg, int* __restrict__ cnt,
    const int* __restrict__ lengths, int* __restrict__ order,
    int* __restrict__ rowptr, int* __restrict__ cursor,
    float* __restrict__ dis, float* __restrict__ dis2) {
    int bid = blockIdx.x;
    int tid = threadIdx.x;
    if (bid < NEDB) {
        // degree + in-count histogram
        int e = bid * 256 + tid;
        int dst = ei[Ee + e];
        atomicAdd(&deg[dst], ea[e]);
        atomicAdd(&cnt[dst], 1);
    } else {
        // rank-sort batches by length (descending)
        __shared__ int sl[NB];
        if (tid < NB) sl[tid] = lengths[tid];
        __syncthreads();
        if (tid < NB) {
            int v = sl[tid];
            int r = 0;
            #pragma unroll
            for (int m = 0; m < NB; m++) {
                int vm = sl[m];
                r += (vm > v) || (vm == v && m < tid);
            }
            order[r] = tid;
        }
    }

    // ---- last-block scan: rowptr/cursor + dis/dis2 ----
    __threadfence();
    __syncthreads();
    __shared__ unsigned rank_s;
    if (tid == 0) rank_s = atomicAdd(&d_done, 1u);
    __syncthreads();
    if (rank_s != NPREB - 1) return;
    __threadfence();    // acquire: all other blocks' writes now visible

    __shared__ int swarp[8];
    int wid = tid >> 5, lane = tid & 31;
    const int4* c4 = (const int4*)cnt;
    int pref[32];
    int s = 0;
    #pragma unroll
    for (int q = 0; q < 8; q++) {
        int4 v = c4[tid * 8 + q];
        pref[4 * q]     = s; s += v.x;
        pref[4 * q + 1] = s; s += v.y;
        pref[4 * q + 2] = s; s += v.z;
        pref[4 * q + 3] = s; s += v.w;
    }
    int sc = s;
    #pragma unroll
    for (int off = 1; off < 32; off <<= 1) {
        int n = __shfl_up_sync(0xffffffffu, sc, off);
        if (lane >= off) sc += n;
    }
    if (lane == 31) swarp[wid] = sc;
    __syncthreads();
    if (tid == 0) {
        int r = 0;
        #pragma unroll
        for (int w = 0; w < 8; w++) { r += swarp[w]; swarp[w] = r; }
    }
    __syncthreads();
    int base = (wid > 0 ? swarp[wid - 1] : 0) + (sc - s);  // exclusive prefix
    int idx0 = tid * 32;
    #pragma unroll
    for (int j = 0; j < 32; j++) {
        int idx = idx0 + j;
        if (idx < Nn) {
            int v = base + pref[j];
            rowptr[idx] = v;
            cursor[idx] = v;
        }
    }
    if (tid == 255) rowptr[Nn] = swarp[7];
    for (int i = tid; i < Nn; i += 256) {
        float dg = deg[i];
        float di = rsqrtf(dg);
        dis[i]  = di;
        dis2[i] = di * di;
    }
}

// ---------------- 3) merged: GRU+gemm0 (bids 0..NGRUB-1) | CSR fill (rest) ----------------
// GRU: 2 nodes per warp, register-resident packed weights (verified round-11 core).
// x read DIRECTLY from [N][T] layout: warp-uniform broadcast loads, one L1 line
// per 32 steps per node -> transpose eliminated.
// Epilogue: block computes xw0 = h @ W0^T for its own 4 nodes (no grid dep).
__global__ void __launch_bounds__(64) gru_csr_kernel(
    const float* __restrict__ x, const int* __restrict__ lengths,
    const int* __restrict__ order,
    const float* __restrict__ W_hh, const float* __restrict__ W_ih,
    const float* __restrict__ b_ih, const float* __restrict__ b_hh,
    const float* __restrict__ W0,
    float* __restrict__ xw_out, __half* __restrict__ xwh_out,
    const int* __restrict__ ei, const float* __restrict__ ea,
    const float* __restrict__ dis, int* __restrict__ cursor,
    ull* __restrict__ edge) {
    int bid = blockIdx.x;
    int tid = threadIdx.x;
    if (bid >= NGRUB) {
        // ---- CSR fill: one edge per thread ----
        int e = (bid - NGRUB) * 64 + tid;
        int src = ei[e];
        int dst = ei[Ee + e];
        float c = dis[src] * ea[e] * dis[dst];
        int pos = atomicAdd(&cursor[dst], 1);
        edge[pos] = ((ull)__float_as_uint(c) << 32) | (unsigned)src;
        return;
    }
    // ---- GRU ----
    __shared__ __align__(16) float sh_h[2][4][32];   // [buf][node-in-block][channel]
    int wid = tid >> 5;          // warp id (2 warps/block)
    int j   = tid & 31;          // hidden channel
    int batch = order[bid / BPB2];
    int nbase = batch * NODES_ + (bid % BPB2) * 4;
    int n0 = nbase + wid * 2;    // nodes n0, n0+1
    int len = lengths[batch];    // uniform across warp

    ull wR[16], wZ[16], wN[16];
    #pragma unroll
    for (int p = 0; p < 16; p++) {
        wR[p] = *(const ull*)&W_hh[(j     ) * 32 + 2 * p];
        wZ[p] = *(const ull*)&W_hh[(32 + j) * 32 + 2 * p];
        wN[p] = *(const ull*)&W_hh[(64 + j) * 32 + 2 * p];
    }
    float wiR = W_ih[j], wiZ = W_ih[32 + j], wiN = W_ih[64 + j];
    float bR  = b_ih[j]      + b_hh[j];
    float bZ  = b_ih[32 + j] + b_hh[32 + j];
    float bNx = b_ih[64 + j];
    float bNh = b_hh[64 + j];

    int ra = wid * 2, rb = wid * 2 + 1;
    float h0 = 0.0f, h1 = 0.0f;
    sh_h[0][ra][j] = 0.0f;
    sh_h[0][rb][j] = 0.0f;
    __syncwarp();

    const longlong2* hrdA = (const longlong2*)sh_h[0][ra];
    const longlong2* hrdB = (const longlong2*)sh_h[0][rb];
    float* hwrA = sh_h[1][ra];
    float* hwrB = sh_h[1][rb];

    const float* xpA = x + n0 * Tt;          // broadcast (uniform) row pointers
    const float* xpB = x + (n0 + 1) * Tt;
    float xn0 = __ldg(&xpA[0]);
    float xn1 = __ldg(&xpB[0]);
    for (int t = 0; t < len; t++) {
        float xt0 = xn0, xt1 = xn1;
        int tn = min(t + 1, Tt - 1);
        xn0 = __ldg(&xpA[tn]);               // L1-resident sequential prefetch
        xn1 = __ldg(&xpB[tn]);

        ull aR0 = pack2_(fmaf(xt0, wiR, bR), 0.0f);
        ull aZ0 = pack2_(fmaf(xt0, wiZ, bZ), 0.0f);
        ull aN0 = pack2_(bNh, 0.0f);
        ull aR1 = pack2_(fmaf(xt1, wiR, bR), 0.0f);
        ull aZ1 = pack2_(fmaf(xt1, wiZ, bZ), 0.0f);
        ull aN1 = pack2_(bNh, 0.0f);
        #pragma unroll
        for (int p = 0; p < 8; p++) {
            longlong2 ha = hrdA[p];          // broadcast LDS.128: 4 h of node 0
            longlong2 hb = hrdB[p];          // broadcast LDS.128: 4 h of node 1
            ull a0 = (ull)ha.x, a1 = (ull)ha.y;
            ull b0 = (ull)hb.x, b1 = (ull)hb.y;
            aR0 = fma2_(a0, wR[2 * p], aR0);
            aR1 = fma2_(b0, wR[2 * p], aR1);
            aZ0 = fma2_(a0, wZ[2 * p], aZ0);
            aZ1 = fma2_(b0, wZ[2 * p], aZ1);
            aN0 = fma2_(a0, wN[2 * p], aN0);
            aN1 = fma2_(b0, wN[2 * p], aN1);
            aR0 = fma2_(a1, wR[2 * p + 1], aR0);
            aR1 = fma2_(b1, wR[2 * p + 1], aR1);
            aZ0 = fma2_(a1, wZ[2 * p + 1], aZ0);
            aZ1 = fma2_(b1, wZ[2 * p + 1], aZ1);
            aN0 = fma2_(a1, wN[2 * p + 1], aN0);
            aN1 = fma2_(b1, wN[2 * p + 1], aN1);
        }
        float r0 = sigm_(hsum2_(aR0));
        float r1 = sigm_(hsum2_(aR1));
        float z0 = sigm_(hsum2_(aZ0));
        float z1 = sigm_(hsum2_(aZ1));
        float nn0 = tanh_(fmaf(xt0, wiN, bNx) + r0 * hsum2_(aN0));
        float nn1 = tanh_(fmaf(xt1, wiN, bNx) + r1 * hsum2_(aN1));
        h0 = fmaf(z0, h0 - nn0, nn0);        // (1-z)*nn + z*h
        h1 = fmaf(z1, h1 - nn1, nn1);
        hwrA[j] = h0;
        hwrB[j] = h1;
        __syncwarp();
        float* tA = (float*)hrdA; hrdA = (const longlong2*)hwrA; hwrA = tA;
        float* tB = (float*)hrdB; hrdB = (const longlong2*)hwrB; hwrB = tB;
    }

    // ---- gemm0 epilogue: xw[n][o] = sum_k h[n][k] * W0[o][k], 4 own nodes ----
    sh_h[0][ra][j] = h0;
    sh_h[0][rb][j] = h1;
    __syncthreads();
    int o = tid;                 // 0..63 output channel
    float4 w[8];
    #pragma unroll
    for (int q = 0; q < 8; q++)
        w[q] = ((const float4*)W0)[o * 8 + q];
    #pragma unroll
    for (int k = 0; k < 4; k++) {
        const float4* hv = (const float4*)sh_h[0][k];
        float acc = 0.0f;
        #pragma unroll
        for (int q = 0; q < 8; q++) {
            float4 hh = hv[q];   // broadcast LDS.128
            acc = fmaf(w[q].x, hh.x, acc);
            acc = fmaf(w[q].y, hh.y, acc);
            acc = fmaf(w[q].z, hh.z, acc);
            acc = fmaf(w[q].w, hh.w, acc);
        }
        int n = nbase + k;
        xw_out[n * 64 + o]  = acc;
        xwh_out[n * 64 + o] = __float2half(acc);
    }
}

// ---------------- 4-7) aggregation (+ fused next-layer gemm) ----------------
// Verified round-11 body: 8 nodes/block, 16 lanes/node, shfl-distributed edge
// records (ONE LDG.64 fetches 16 edges). fp16 gathers, fp32 accumulation.
// If Wnext != null: block also computes xw_{i+1} for its own 8 nodes.
__global__ void __launch_bounds__(128) agg_kernel(
    const float* __restrict__ xw, const __half* __restrict__ xwh,
    const float* __restrict__ dis2,
    const int* __restrict__ rowptr, const ull* __restrict__ edge,
    const float* __restrict__ bias,
    const float* __restrict__ prelu_a, int layer,
    const float* __restrict__ Wnext,
    float* __restrict__ xw_out, __half* __restrict__ xwh_out,
    float* __restrict__ final_out) {
    __shared__ __align__(16) float sh_res[8][64];
    int tid = threadIdx.x;           // 128 -> 8 nodes per block, 16 lanes per node
    int n = blockIdx.x * 8 + (tid >> 4);
    int l = tid & 15;
    int lane = tid & 31;
    unsigned gmask = 0xFFFFu << (lane & 16);

    const float4* __restrict__ xw4 = (const float4*)xw;
    const uint2* __restrict__ xh = (const uint2*)xwh;   // 4 halves per element
    float4 acc = xw4[n * 16 + l];
    float d2 = dis2[n];
    acc.x *= d2; acc.y *= d2; acc.z *= d2; acc.w *= d2;

    int e0 = rowptr[n], e1 = rowptr[n + 1];
    for (int e = e0; e < e1; e += 16) {
        ull rec = 0;                              // zero coef pads partial chunks
        if (e + l < e1) rec = edge[e + l];
        #pragma unroll
        for (int m = 0; m < 16; m++) {
            ull rm = __shfl_sync(gmask, rec, m, 16);
            int   sm = (int)(unsigned)rm;
            float cm = __uint_as_float((unsigned)(rm >> 32));
            uint2 hv = xh[sm * 16 + l];
            float2 f0 = __half22float2(*(__half2*)&hv.x);
            float2 f1 = __half22float2(*(__half2*)&hv.y);
            acc.x = fmaf(cm, f0.x, acc.x); acc.y = fmaf(cm, f0.y, acc.y);
            acc.z = fmaf(cm, f1.x, acc.z); acc.w = fmaf(cm, f1.y, acc.w);
        }
    }
    float4 b4 = ((const float4*)bias)[l];
    acc.x += b4.x; acc.y += b4.y; acc.z += b4.z; acc.w += b4.w;
    float a = prelu_a[layer];
    acc.x = (acc.x >= 0.f) ? acc.x : a * acc.x;
    acc.y = (acc.y >= 0.f) ? acc.y : a * acc.y;
    acc.z = (acc.z >= 0.f) ? acc.z : a * acc.z;
    acc.w = (acc.w >= 0.f) ? acc.w : a * acc.w;

    if (Wnext == nullptr) {          // final layer: write node embeddings
        ((float4*)final_out)[n * 16 + l] = acc;
        return;
    }
    ((float4*)sh_res[tid >> 4])[l] = acc;
    __syncthreads();

    // ---- fused gemm: xw_{i+1}[n][o] = sum_k res[n][k] * Wnext[o][k], 8 own nodes ----
    int o = tid & 63;
    int half = tid >> 6;             // 0 or 1
    int nbase = blockIdx.x * 8;
    #pragma unroll
    for (int k = 0; k < 4; k++) {
        int nl = k * 2 + half;
        const float4* hv = (const float4*)sh_res[nl];
        const float4* wr = (const float4*)Wnext + o * 16;
        float acc2 = 0.0f;
        #pragma unroll
        for (int q = 0; q < 16; q++) {
            float4 hh = hv[q];
            float4 ww = wr[q];
            acc2 = fmaf(ww.x, hh.x, acc2);
            acc2 = fmaf(ww.y, hh.y, acc2);
            acc2 = fmaf(ww.z, hh.z, acc2);
            acc2 = fmaf(ww.w, hh.w, acc2);
        }
        int n2 = nbase + nl;
        xw_out[n2 * 64 + o]  = acc2;
        xwh_out[n2 * 64 + o] = __float2half(acc2);
    }
}

// ---------------- 8) graph mean pooling ----------------
__global__ void graph_kernel(const float* __restrict__ node_emb, float* __restrict__ gout) {
    int b = blockIdx.x;   // 64
    int d = threadIdx.x;  // 64
    float s = 0.0f;
    #pragma unroll 8
    for (int i = 0; i < NODES_; i++)
        s += node_emb[(b * NODES_ + i) * 64 + d];
    gout[b * 64 + d] = s * (1.0f / (float)NODES_);
}

// ---------------- launch (8 kernels, single stream) ----------------
extern "C" void kernel_launch(void* const* d_in, const int* in_sizes, int n_in,
                              void* d_out, int out_size) {
    const float* x       = (const float*)d_in[0];
    const int*   ei      = (const int*)d_in[1];
    const float* ea      = (const float*)d_in[2];
    const int*   lengths = (const int*)d_in[3];
    // d_in[4] = batch (unused; batch[n] == n / NODES_)
    const float* W_ih    = (const float*)d_in[5];
    const float* W_hh    = (const float*)d_in[6];
    const float* b_ih    = (const float*)d_in[7];
    const float* b_hh    = (const float*)d_in[8];
    const float* g_w0    = (const float*)d_in[9];
    const float* g_b0    = (const float*)d_in[10];
    const float* g_ws    = (const float*)d_in[11];
    const float* g_bs    = (const float*)d_in[12];
    const float* prelu_a = (const float*)d_in[13];
    float* out = (float*)d_out;

    float *xwA, *xwB, *deg, *dis, *dis2;
    __half *xwhA, *xwhB;
    int *cnt, *rowptr, *cursor, *order;
    ull* edge;
    cudaGetSymbolAddress((void**)&xwA,    d_xwA);
    cudaGetSymbolAddress((void**)&xwhA,   d_xwhA);
    cudaGetSymbolAddress((void**)&xwB,    d_xwB);
    cudaGetSymbolAddress((void**)&xwhB,   d_xwhB);
    cudaGetSymbolAddress((void**)&deg,    d_deg);
    cudaGetSymbolAddress((void**)&dis,    d_dis);
    cudaGetSymbolAddress((void**)&dis2,   d_dis2);
    cudaGetSymbolAddress((void**)&cnt,    d_cnt);
    cudaGetSymbolAddress((void**)&rowptr, d_rowptr);
    cudaGetSymbolAddress((void**)&cursor, d_cursor);
    cudaGetSymbolAddress((void**)&order,  d_order);
    cudaGetSymbolAddress((void**)&edge,   d_edge);

    // 1: init deg/cnt/done
    init_kernel<<<8192 / 256, 256>>>(deg, cnt);
    // 2: fused edge_deg | sort  (+ last-block scan)
    fused_pre_kernel<<<NPREB, 256>>>(ei, ea, deg, cnt, lengths, order,
                                     rowptr, cursor, dis, dis2);
    // 3: merged GRU+gemm0 | CSR fill  (x read directly, no transpose)
    gru_csr_kernel<<<NGRUB + NCSRB, 64>>>(x, lengths, order, W_hh, W_ih, b_ih, b_hh,
                                          g_w0, xwA, xwhA, ei, ea, dis, cursor, edge);
    // 4-7: agg layers (each fuses the next layer's gemm); A/B ping-pong
    agg_kernel<<<Nn / 8, 128>>>(xwA, xwhA, dis2, rowptr, edge, g_b0, prelu_a, 0,
                                g_ws + 0 * 64 * 64, xwB, xwhB, nullptr);      // profiled
    agg_kernel<<<Nn / 8, 128>>>(xwB, xwhB, dis2, rowptr, edge, g_bs + 0 * 64, prelu_a, 1,
                                g_ws + 1 * 64 * 64, xwA, xwhA, nullptr);
    agg_kernel<<<Nn / 8, 128>>>(xwA, xwhA, dis2, rowptr, edge, g_bs + 1 * 64, prelu_a, 2,
                                g_ws + 2 * 64 * 64, xwB, xwhB, nullptr);
    agg_kernel<<<Nn / 8, 128>>>(xwB, xwhB, dis2, rowptr, edge, g_bs + 2 * 64, prelu_a, 3,
                                nullptr, nullptr, nullptr, out);
    // 8: graph embedding appended after node embeddings
    graph_kernel<<<NB, 64>>>(out, out + Nn * 64);
}